// round 1
// baseline (speedup 1.0000x reference)
#include <cuda_runtime.h>
#include <cuda_fp16.h>

#define BN 8192
#define DN 128
#define KN 256
#define INV_T (1.0f / 0.07f)

// Scratch (no allocations allowed in kernel_launch)
__device__ float  g_z1n[BN * DN];      // normalized z1, fp32 (4 MB)
__device__ __half g_z2h[BN * DN];      // normalized z2, fp16 (2 MB, L2-resident)
__device__ float  g_pos[BN];           // positive logit per row (fp32-exact path)
__device__ float  g_partial[BN];       // per-row loss
__device__ int    g_is64;              // index dtype flag

// ---------------------------------------------------------------------------
// Detect whether negative_samples is int64 or int32 (JAX x64 ambiguity).
// Values are in [0, 8192), so for int64 little-endian the high 32-bit word of
// every element is 0. Probability of 64 consecutive genuine int32 indices all
// being zero at odd positions is (1/8192)^64 ~ 0.
// ---------------------------------------------------------------------------
__global__ void detect_kernel(const int* __restrict__ raw) {
    if (threadIdx.x == 0 && blockIdx.x == 0) {
        int is64 = 1;
        #pragma unroll 1
        for (int i = 0; i < 64; i++) {
            if (raw[2 * i + 1] != 0) { is64 = 0; break; }
        }
        g_is64 = is64;
    }
}

// ---------------------------------------------------------------------------
// Normalize z1 (fp32 out) and z2 (fp16 out); compute positive logit in fp32.
// One warp per row, 4 elements per lane (float4).
// ---------------------------------------------------------------------------
__global__ void norm_kernel(const float* __restrict__ z1,
                            const float* __restrict__ z2) {
    const int warp = threadIdx.x >> 5;
    const int lane = threadIdx.x & 31;
    const int row  = blockIdx.x * 8 + warp;
    if (row >= BN) return;

    float4 a = reinterpret_cast<const float4*>(z1 + (size_t)row * DN)[lane];
    float4 b = reinterpret_cast<const float4*>(z2 + (size_t)row * DN)[lane];

    float sa = a.x * a.x + a.y * a.y + a.z * a.z + a.w * a.w;
    float sb = b.x * b.x + b.y * b.y + b.z * b.z + b.w * b.w;
    #pragma unroll
    for (int o = 16; o; o >>= 1) {
        sa += __shfl_xor_sync(0xffffffffu, sa, o);
        sb += __shfl_xor_sync(0xffffffffu, sb, o);
    }
    const float inva = 1.0f / fmaxf(sqrtf(sa), 1e-12f);
    const float invb = 1.0f / fmaxf(sqrtf(sb), 1e-12f);

    a.x *= inva; a.y *= inva; a.z *= inva; a.w *= inva;
    b.x *= invb; b.y *= invb; b.z *= invb; b.w *= invb;

    reinterpret_cast<float4*>(g_z1n + (size_t)row * DN)[lane] = a;
    __half2* hrow = reinterpret_cast<__half2*>(g_z2h + (size_t)row * DN);
    hrow[lane * 2 + 0] = __floats2half2_rn(b.x, b.y);
    hrow[lane * 2 + 1] = __floats2half2_rn(b.z, b.w);

    // positive similarity in full fp32 (matches reference path closely)
    float d = a.x * b.x + a.y * b.y + a.z * b.z + a.w * b.w;
    #pragma unroll
    for (int o = 16; o; o >>= 1) d += __shfl_xor_sync(0xffffffffu, d, o);
    if (lane == 0) g_pos[row] = d * INV_T;
}

// ---------------------------------------------------------------------------
// Per-row negatives: block = row, thread = one negative (K=256 threads).
// fp16 gather (256 B/row -> half the L2 traffic of fp32), fp32 accumulate.
// ---------------------------------------------------------------------------
__global__ void __launch_bounds__(256)
gather_kernel(const int* __restrict__ raw) {
    __shared__ float s_z1[DN];
    __shared__ float s_red[8];

    const int b = blockIdx.x;
    const int t = threadIdx.x;

    if (t < DN) s_z1[t] = g_z1n[(size_t)b * DN + t];
    __syncthreads();

    const int kidx = b * KN + t;
    const int idx  = g_is64 ? raw[2 * kidx] : raw[kidx];

    const float4* p4 =
        reinterpret_cast<const float4*>(g_z2h + (size_t)idx * DN);

    float acc = 0.0f;
    #pragma unroll
    for (int i = 0; i < 16; i++) {
        float4 v = p4[i];
        float2 f0 = __half22float2(*reinterpret_cast<__half2*>(&v.x));
        float2 f1 = __half22float2(*reinterpret_cast<__half2*>(&v.y));
        float2 f2 = __half22float2(*reinterpret_cast<__half2*>(&v.z));
        float2 f3 = __half22float2(*reinterpret_cast<__half2*>(&v.w));
        const float* w = s_z1 + i * 8;
        acc = fmaf(f0.x, w[0], acc);
        acc = fmaf(f0.y, w[1], acc);
        acc = fmaf(f1.x, w[2], acc);
        acc = fmaf(f1.y, w[3], acc);
        acc = fmaf(f2.x, w[4], acc);
        acc = fmaf(f2.y, w[5], acc);
        acc = fmaf(f3.x, w[6], acc);
        acc = fmaf(f3.y, w[7], acc);
    }

    // exp of this negative's logit; |logit| <= 14.3 so no max-shift needed
    float e = expf(acc * INV_T);

    #pragma unroll
    for (int o = 16; o; o >>= 1) e += __shfl_xor_sync(0xffffffffu, e, o);
    if ((t & 31) == 0) s_red[t >> 5] = e;
    __syncthreads();

    if (t == 0) {
        float tot = 0.0f;
        #pragma unroll
        for (int i = 0; i < 8; i++) tot += s_red[i];
        const float pos = g_pos[b];
        tot += expf(pos);
        g_partial[b] = logf(tot) - pos;   // -log_softmax(logits)[0]
    }
}

// ---------------------------------------------------------------------------
// Deterministic mean of per-row losses.
// ---------------------------------------------------------------------------
__global__ void reduce_kernel(float* __restrict__ out) {
    __shared__ float s[256];
    const int t = threadIdx.x;
    float a = 0.0f;
    for (int i = t; i < BN; i += 256) a += g_partial[i];
    s[t] = a;
    __syncthreads();
    #pragma unroll
    for (int o = 128; o; o >>= 1) {
        if (t < o) s[t] += s[t + o];
        __syncthreads();
    }
    if (t == 0) out[0] = s[0] / (float)BN;
}

extern "C" void kernel_launch(void* const* d_in, const int* in_sizes, int n_in,
                              void* d_out, int out_size) {
    const float* z1  = (const float*)d_in[0];
    const float* z2  = (const float*)d_in[1];
    const int*   neg = (const int*)d_in[2];   // raw view; width detected on-device
    float* out = (float*)d_out;

    detect_kernel<<<1, 32>>>(neg);
    norm_kernel<<<BN / 8, 256>>>(z1, z2);
    gather_kernel<<<BN, 256>>>(neg);
    reduce_kernel<<<1, 256>>>(out);
}

// round 2
// speedup vs baseline: 2.6897x; 2.6897x over previous
#include <cuda_runtime.h>
#include <cuda_fp16.h>

#define BN 8192
#define DN 128
#define KN 256
#define INV_T (1.0f / 0.07f)

// Scratch (no allocations allowed anywhere)
__device__ float  g_z1n[BN * DN];      // normalized z1, fp32 (4 MB)
__device__ __half g_z2h[BN * DN];      // normalized z2, fp16 (2 MB, L2-resident)
__device__ float  g_pos[BN];           // positive logit per row (fp32 path)
__device__ float  g_partial[BN];       // per-row loss
__device__ int    g_is64;              // index dtype flag

// ---------------------------------------------------------------------------
// Parallel dtype detection: values are in [0,8192), so for little-endian int64
// every high 32-bit word is 0. 64 threads check 64 words in parallel.
// ---------------------------------------------------------------------------
__global__ void detect_kernel(const int* __restrict__ raw) {
    const int t = threadIdx.x;                 // 64 threads
    const int nz = (raw[2 * t + 1] != 0) ? 1 : 0;
    const unsigned any = __ballot_sync(0xffffffffu, nz);
    __shared__ unsigned s[2];
    if ((t & 31) == 0) s[t >> 5] = any;
    __syncthreads();
    if (t == 0) g_is64 = ((s[0] | s[1]) == 0u) ? 1 : 0;
}

// ---------------------------------------------------------------------------
// Normalize z1 (fp32 out) and z2 (fp16 out); compute positive logit in fp32.
// One warp per row, 4 elements per lane (float4).
// ---------------------------------------------------------------------------
__global__ void norm_kernel(const float* __restrict__ z1,
                            const float* __restrict__ z2) {
    const int warp = threadIdx.x >> 5;
    const int lane = threadIdx.x & 31;
    const int row  = blockIdx.x * 8 + warp;
    if (row >= BN) return;

    float4 a = reinterpret_cast<const float4*>(z1 + (size_t)row * DN)[lane];
    float4 b = reinterpret_cast<const float4*>(z2 + (size_t)row * DN)[lane];

    float sa = a.x * a.x + a.y * a.y + a.z * a.z + a.w * a.w;
    float sb = b.x * b.x + b.y * b.y + b.z * b.z + b.w * b.w;
    #pragma unroll
    for (int o = 16; o; o >>= 1) {
        sa += __shfl_xor_sync(0xffffffffu, sa, o);
        sb += __shfl_xor_sync(0xffffffffu, sb, o);
    }
    const float inva = 1.0f / fmaxf(sqrtf(sa), 1e-12f);
    const float invb = 1.0f / fmaxf(sqrtf(sb), 1e-12f);

    a.x *= inva; a.y *= inva; a.z *= inva; a.w *= inva;
    b.x *= invb; b.y *= invb; b.z *= invb; b.w *= invb;

    reinterpret_cast<float4*>(g_z1n + (size_t)row * DN)[lane] = a;
    __half2* hrow = reinterpret_cast<__half2*>(g_z2h + (size_t)row * DN);
    hrow[lane * 2 + 0] = __floats2half2_rn(b.x, b.y);
    hrow[lane * 2 + 1] = __floats2half2_rn(b.z, b.w);

    float d = a.x * b.x + a.y * b.y + a.z * b.z + a.w * b.w;
    #pragma unroll
    for (int o = 16; o; o >>= 1) d += __shfl_xor_sync(0xffffffffu, d, o);
    if (lane == 0) g_pos[row] = d * INV_T;
}

// ---------------------------------------------------------------------------
// Gather v2: one z2 row per HALF-WARP (16 lanes x 16B = one 256B row), so a
// single LDG.128 pulls 2 complete rows touching only 4 cache lines
// (4 L1tex wavefronts instead of 32). Block = one z1 row b; warp w handles
// negatives [w*32, w*32+32), 2 rows per iteration, 16 iterations.
// Lane `i` of each half-warp "owns" the dot of its half's i-th iteration row,
// so every thread does exactly one expf at the end.
// ---------------------------------------------------------------------------
__global__ void __launch_bounds__(256)
gather_kernel(const int* __restrict__ raw) {
    const int b    = blockIdx.x;
    const int t    = threadIdx.x;
    const int w    = t >> 5;
    const int lane = t & 31;
    const int hl   = lane & 15;   // lane within half-warp
    const int hw   = lane >> 4;   // which half (0/1)

    // z1 segment for this lane: elements [hl*8, hl*8+8) in registers.
    const float4* z1p =
        reinterpret_cast<const float4*>(g_z1n + (size_t)b * DN) + hl * 2;
    const float4 z1a = z1p[0];
    const float4 z1b = z1p[1];

    // Each lane loads one negative index (coalesced).
    const int kbase = b * KN + w * 32 + lane;
    const int myidx = g_is64 ? raw[2 * kbase] : raw[kbase];

    float mydot = 0.0f;
    #pragma unroll
    for (int i = 0; i < 16; i++) {
        const int row = __shfl_sync(0xffffffffu, myidx, 2 * i + hw);
        float4 v = reinterpret_cast<const float4*>(g_z2h + (size_t)row * DN)[hl];
        const float2 f0 = __half22float2(*reinterpret_cast<__half2*>(&v.x));
        const float2 f1 = __half22float2(*reinterpret_cast<__half2*>(&v.y));
        const float2 f2 = __half22float2(*reinterpret_cast<__half2*>(&v.z));
        const float2 f3 = __half22float2(*reinterpret_cast<__half2*>(&v.w));
        float p = f0.x * z1a.x;
        p = fmaf(f0.y, z1a.y, p);
        p = fmaf(f1.x, z1a.z, p);
        p = fmaf(f1.y, z1a.w, p);
        p = fmaf(f2.x, z1b.x, p);
        p = fmaf(f2.y, z1b.y, p);
        p = fmaf(f3.x, z1b.z, p);
        p = fmaf(f3.y, z1b.w, p);
        // reduce across the 16 lanes of this half-warp
        p += __shfl_xor_sync(0xffffffffu, p, 8);
        p += __shfl_xor_sync(0xffffffffu, p, 4);
        p += __shfl_xor_sync(0xffffffffu, p, 2);
        p += __shfl_xor_sync(0xffffffffu, p, 1);
        if (hl == i) mydot = p;   // lane i owns iteration i's row dot
    }

    // One exp per thread; |logit| <= 14.3, so no max-shift needed in fp32.
    float e = expf(mydot * INV_T);
    #pragma unroll
    for (int o = 16; o; o >>= 1) e += __shfl_xor_sync(0xffffffffu, e, o);

    __shared__ float s_red[8];
    if (lane == 0) s_red[w] = e;
    __syncthreads();

    if (t == 0) {
        float tot = s_red[0] + s_red[1] + s_red[2] + s_red[3]
                  + s_red[4] + s_red[5] + s_red[6] + s_red[7];
        const float pos = g_pos[b];
        tot += expf(pos);
        g_partial[b] = logf(tot) - pos;   // -log_softmax(logits)[0]
    }
}

// ---------------------------------------------------------------------------
// Deterministic mean of per-row losses: 1024 threads, float4 loads.
// ---------------------------------------------------------------------------
__global__ void __launch_bounds__(1024)
reduce_kernel(float* __restrict__ out) {
    __shared__ float s[1024];
    const int t = threadIdx.x;
    const float4* p = reinterpret_cast<const float4*>(g_partial);
    const float4 a = p[t];
    const float4 b = p[t + 1024];
    s[t] = (a.x + a.y + a.z + a.w) + (b.x + b.y + b.z + b.w);
    __syncthreads();
    #pragma unroll
    for (int o = 512; o; o >>= 1) {
        if (t < o) s[t] += s[t + o];
        __syncthreads();
    }
    if (t == 0) out[0] = s[0] / (float)BN;
}

extern "C" void kernel_launch(void* const* d_in, const int* in_sizes, int n_in,
                              void* d_out, int out_size) {
    const float* z1  = (const float*)d_in[0];
    const float* z2  = (const float*)d_in[1];
    const int*   neg = (const int*)d_in[2];   // raw view; width detected on-device
    float* out = (float*)d_out;

    detect_kernel<<<1, 64>>>(neg);
    norm_kernel<<<BN / 8, 256>>>(z1, z2);
    gather_kernel<<<BN, 256>>>(neg);
    reduce_kernel<<<1, 1024>>>(out);
}

// round 3
// speedup vs baseline: 3.3704x; 1.2531x over previous
#include <cuda_runtime.h>
#include <cuda_fp16.h>
#include <cuda_fp8.h>

#define BN 8192
#define DN 128
#define KN 256
#define INV_T (1.0f / 0.07f)
#define Z2_SCALE 8.0f                 // pre-scale before fp8 to avoid subnormals
#define LOGIT_SCALE (INV_T / Z2_SCALE)

// Scratch (no allocations allowed anywhere)
__device__ __half g_z1h[BN * DN];     // normalized z1, fp16 (2 MB)
__device__ uint4  g_z2q[BN * DN / 16];// normalized z2 * 8, e4m3 (1 MB; row = 128B = 1 L2 line)
__device__ float  g_pos[BN];          // positive logit (fp32-exact path)
__device__ float  g_partial[BN];      // per-row loss
__device__ int    g_is64;             // index dtype flag
__device__ int    g_count;            // last-block-done counter (reset by norm each replay)

// ---------------------------------------------------------------------------
// Normalize z1 -> fp16, z2 -> e4m3*8; positive logit in fp32.
// One warp per row. Block 0 / warp 0 additionally detects the index dtype
// (values < 8192, so int64 little-endian => all odd 32-bit words are 0) and
// resets the completion counter for this graph replay.
// ---------------------------------------------------------------------------
__global__ void norm_kernel(const float* __restrict__ z1,
                            const float* __restrict__ z2,
                            const int* __restrict__ raw) {
    const int warp = threadIdx.x >> 5;
    const int lane = threadIdx.x & 31;

    if (blockIdx.x == 0 && warp == 0) {
        const int nz = (raw[2 * lane + 1] != 0) | (raw[2 * (lane + 32) + 1] != 0);
        const unsigned bal = __ballot_sync(0xffffffffu, nz);
        if (lane == 0) { g_is64 = (bal == 0u) ? 1 : 0; g_count = 0; }
    }

    const int row = blockIdx.x * 8 + warp;
    if (row >= BN) return;

    float4 a = reinterpret_cast<const float4*>(z1 + (size_t)row * DN)[lane];
    float4 b = reinterpret_cast<const float4*>(z2 + (size_t)row * DN)[lane];

    float sa = a.x * a.x + a.y * a.y + a.z * a.z + a.w * a.w;
    float sb = b.x * b.x + b.y * b.y + b.z * b.z + b.w * b.w;
    #pragma unroll
    for (int o = 16; o; o >>= 1) {
        sa += __shfl_xor_sync(0xffffffffu, sa, o);
        sb += __shfl_xor_sync(0xffffffffu, sb, o);
    }
    const float inva = 1.0f / fmaxf(sqrtf(sa), 1e-12f);
    const float invb = 1.0f / fmaxf(sqrtf(sb), 1e-12f);

    a.x *= inva; a.y *= inva; a.z *= inva; a.w *= inva;
    b.x *= invb; b.y *= invb; b.z *= invb; b.w *= invb;

    // z1 -> fp16
    __half2* h1 = reinterpret_cast<__half2*>(g_z1h + (size_t)row * DN);
    h1[lane * 2 + 0] = __floats2half2_rn(a.x, a.y);
    h1[lane * 2 + 1] = __floats2half2_rn(a.z, a.w);

    // z2 * 8 -> e4m3, 4 bytes per lane
    const __nv_fp8x2_storage_t lo = __nv_cvt_float2_to_fp8x2(
        make_float2(b.x * Z2_SCALE, b.y * Z2_SCALE), __NV_SATFINITE, __NV_E4M3);
    const __nv_fp8x2_storage_t hi = __nv_cvt_float2_to_fp8x2(
        make_float2(b.z * Z2_SCALE, b.w * Z2_SCALE), __NV_SATFINITE, __NV_E4M3);
    reinterpret_cast<unsigned*>(g_z2q)[(size_t)row * 32 + lane] =
        (unsigned)lo | ((unsigned)hi << 16);

    // positive logit, full fp32
    float d = a.x * b.x + a.y * b.y + a.z * b.z + a.w * b.w;
    #pragma unroll
    for (int o = 16; o; o >>= 1) d += __shfl_xor_sync(0xffffffffu, d, o);
    if (lane == 0) g_pos[row] = d * INV_T;
}

__device__ __forceinline__ __half2 fp8x2_to_h2(unsigned short v) {
    const __half2_raw r = __nv_cvt_fp8x2_to_halfraw2((__nv_fp8x2_storage_t)v, __NV_E4M3);
    return *reinterpret_cast<const __half2*>(&r);
}

// ---------------------------------------------------------------------------
// Gather v3: fp8 rows (128B = one L2 line). One z2 row per 8-LANE group; a
// single LDG.128 pulls 4 complete rows touching 4 lines. HFMA2 dot, fp32
// group-reduce (3 shuffles). 8 iterations x 4 rows = warp's 32 negatives,
// each lane ends up owning exactly one dot -> one __expf per thread.
// The last block to finish also performs the deterministic mean.
// ---------------------------------------------------------------------------
__global__ void __launch_bounds__(256)
gather_kernel(const int* __restrict__ raw, float* __restrict__ out) {
    __shared__ float s_red[8];
    __shared__ float s_sum[256];
    __shared__ bool  s_last;

    const int b    = blockIdx.x;
    const int t    = threadIdx.x;
    const int w    = t >> 5;
    const int lane = t & 31;
    const int s    = lane & 7;    // lane within 8-lane row group
    const int q    = lane >> 3;   // which of 4 rows per LDG wave

    // z1 fp16 segment for this lane: elements [s*16, s*16+16) -> 8 half2 regs.
    const float4* z1p =
        reinterpret_cast<const float4*>(g_z1h + (size_t)b * DN) + s * 2;
    const float4 za = z1p[0];
    const float4 zb = z1p[1];
    __half2 z1h[8];
    z1h[0] = *reinterpret_cast<const __half2*>(&za.x);
    z1h[1] = *reinterpret_cast<const __half2*>(&za.y);
    z1h[2] = *reinterpret_cast<const __half2*>(&za.z);
    z1h[3] = *reinterpret_cast<const __half2*>(&za.w);
    z1h[4] = *reinterpret_cast<const __half2*>(&zb.x);
    z1h[5] = *reinterpret_cast<const __half2*>(&zb.y);
    z1h[6] = *reinterpret_cast<const __half2*>(&zb.z);
    z1h[7] = *reinterpret_cast<const __half2*>(&zb.w);

    const int kbase = b * KN + w * 32 + lane;
    const int myidx = g_is64 ? raw[2 * kbase] : raw[kbase];

    float mydot = 0.0f;
    #pragma unroll
    for (int i = 0; i < 8; i++) {
        const int row = __shfl_sync(0xffffffffu, myidx, 4 * i + q);
        const uint4 v = g_z2q[(size_t)row * 8 + s];   // 16 e4m3 values
        __half2 acc = __floats2half2_rn(0.0f, 0.0f);
        acc = __hfma2(fp8x2_to_h2((unsigned short)(v.x      )), z1h[0], acc);
        acc = __hfma2(fp8x2_to_h2((unsigned short)(v.x >> 16)), z1h[1], acc);
        acc = __hfma2(fp8x2_to_h2((unsigned short)(v.y      )), z1h[2], acc);
        acc = __hfma2(fp8x2_to_h2((unsigned short)(v.y >> 16)), z1h[3], acc);
        acc = __hfma2(fp8x2_to_h2((unsigned short)(v.z      )), z1h[4], acc);
        acc = __hfma2(fp8x2_to_h2((unsigned short)(v.z >> 16)), z1h[5], acc);
        acc = __hfma2(fp8x2_to_h2((unsigned short)(v.w      )), z1h[6], acc);
        acc = __hfma2(fp8x2_to_h2((unsigned short)(v.w >> 16)), z1h[7], acc);
        const float2 f = __half22float2(acc);
        float p = f.x + f.y;
        p += __shfl_xor_sync(0xffffffffu, p, 4);
        p += __shfl_xor_sync(0xffffffffu, p, 2);
        p += __shfl_xor_sync(0xffffffffu, p, 1);
        if (s == i) mydot = p;    // lane owns negative w*32 + 4*s + q
    }

    // |logit| <= ~14.3 -> no max-shift needed in fp32.
    float e = __expf(mydot * LOGIT_SCALE);
    #pragma unroll
    for (int o = 16; o; o >>= 1) e += __shfl_xor_sync(0xffffffffu, e, o);
    if (lane == 0) s_red[w] = e;
    __syncthreads();

    if (t == 0) {
        float tot = s_red[0] + s_red[1] + s_red[2] + s_red[3]
                  + s_red[4] + s_red[5] + s_red[6] + s_red[7];
        const float pos = g_pos[b];
        tot += __expf(pos);
        g_partial[b] = logf(tot) - pos;   // -log_softmax(logits)[0]
        __threadfence();
        const int c = atomicAdd(&g_count, 1);
        s_last = (c == BN - 1);
    }
    __syncthreads();

    // Last finishing block performs the mean (deterministic order).
    if (s_last) {
        const float4* p4 = reinterpret_cast<const float4*>(g_partial);
        float a = 0.0f;
        #pragma unroll
        for (int j = 0; j < 8; j++) {
            const float4 v = __ldcg(p4 + t + j * 256);
            a += (v.x + v.y) + (v.z + v.w);
        }
        s_sum[t] = a;
        __syncthreads();
        #pragma unroll
        for (int o = 128; o; o >>= 1) {
            if (t < o) s_sum[t] += s_sum[t + o];
            __syncthreads();
        }
        if (t == 0) out[0] = s_sum[0] / (float)BN;
    }
}

extern "C" void kernel_launch(void* const* d_in, const int* in_sizes, int n_in,
                              void* d_out, int out_size) {
    const float* z1  = (const float*)d_in[0];
    const float* z2  = (const float*)d_in[1];
    const int*   neg = (const int*)d_in[2];   // raw view; width detected on-device
    float* out = (float*)d_out;

    norm_kernel<<<BN / 8, 256>>>(z1, z2, neg);
    gather_kernel<<<BN, 256>>>(neg, out);
}

// round 6
// speedup vs baseline: 4.2000x; 1.2462x over previous
#include <cuda_runtime.h>
#include <cuda_fp16.h>

#define BN 8192
#define DN 128
#define KN 256
#define INV_T (1.0f / 0.07f)

// Scratch (no allocations allowed anywhere)
__device__ unsigned g_z1q[BN * DN / 4];  // z1n quantized int8, per-row scale (1 MB)
__device__ unsigned g_z2q[BN * DN / 4];  // z2n quantized int8 * 127       (1 MB)
__device__ float    g_f1[BN];            // per-row logit factor: maxa*INV_T/(127*127)
__device__ float    g_pos[BN];           // positive logit (fp32-exact path)
__device__ float    g_partial[BN];       // per-row loss
__device__ int      g_is64;              // index dtype flag
__device__ int      g_count;             // last-block counter (reset each replay)

// ---------------------------------------------------------------------------
// Normalize z1/z2 in fp32; quantize both to int8 (z1 per-row scale, z2 flat
// 127); positive logit in full fp32. One warp per row. Block 0 / warp 0 also
// detects index dtype (values < 8192 => int64 has all-zero high words) and
// resets the completion counter for this graph replay.
// ---------------------------------------------------------------------------
__global__ void norm_kernel(const float* __restrict__ z1,
                            const float* __restrict__ z2,
                            const int* __restrict__ raw) {
    const int warp = threadIdx.x >> 5;
    const int lane = threadIdx.x & 31;

    if (blockIdx.x == 0 && warp == 0) {
        const int nz = (raw[2 * lane + 1] != 0) | (raw[2 * (lane + 32) + 1] != 0);
        const unsigned bal = __ballot_sync(0xffffffffu, nz);
        if (lane == 0) { g_is64 = (bal == 0u) ? 1 : 0; g_count = 0; }
    }

    const int row = blockIdx.x * 8 + warp;
    if (row >= BN) return;

    float4 a = reinterpret_cast<const float4*>(z1 + (size_t)row * DN)[lane];
    float4 b = reinterpret_cast<const float4*>(z2 + (size_t)row * DN)[lane];

    float sa = a.x * a.x + a.y * a.y + a.z * a.z + a.w * a.w;
    float sb = b.x * b.x + b.y * b.y + b.z * b.z + b.w * b.w;
    #pragma unroll
    for (int o = 16; o; o >>= 1) {
        sa += __shfl_xor_sync(0xffffffffu, sa, o);
        sb += __shfl_xor_sync(0xffffffffu, sb, o);
    }
    const float inva = 1.0f / fmaxf(sqrtf(sa), 1e-12f);
    const float invb = 1.0f / fmaxf(sqrtf(sb), 1e-12f);

    a.x *= inva; a.y *= inva; a.z *= inva; a.w *= inva;
    b.x *= invb; b.y *= invb; b.z *= invb; b.w *= invb;

    // per-row max |z1 elem| for tight quantization scale
    float m = fmaxf(fmaxf(fabsf(a.x), fabsf(a.y)), fmaxf(fabsf(a.z), fabsf(a.w)));
    #pragma unroll
    for (int o = 16; o; o >>= 1) m = fmaxf(m, __shfl_xor_sync(0xffffffffu, m, o));
    m = fmaxf(m, 1e-12f);
    const float s1 = 127.0f / m;

    const int qa0 = __float2int_rn(a.x * s1);
    const int qa1 = __float2int_rn(a.y * s1);
    const int qa2 = __float2int_rn(a.z * s1);
    const int qa3 = __float2int_rn(a.w * s1);
    g_z1q[(size_t)row * 32 + lane] =
        (qa0 & 0xff) | ((qa1 & 0xff) << 8) | ((qa2 & 0xff) << 16) | (qa3 << 24);

    const int qb0 = __float2int_rn(b.x * 127.0f);
    const int qb1 = __float2int_rn(b.y * 127.0f);
    const int qb2 = __float2int_rn(b.z * 127.0f);
    const int qb3 = __float2int_rn(b.w * 127.0f);
    g_z2q[(size_t)row * 32 + lane] =
        (qb0 & 0xff) | ((qb1 & 0xff) << 8) | ((qb2 & 0xff) << 16) | (qb3 << 24);

    if (lane == 0) g_f1[row] = m * (INV_T / (127.0f * 127.0f));

    // positive logit, full fp32
    float d = a.x * b.x + a.y * b.y + a.z * b.z + a.w * b.w;
    #pragma unroll
    for (int o = 16; o; o >>= 1) d += __shfl_xor_sync(0xffffffffu, d, o);
    if (lane == 0) g_pos[row] = d * INV_T;
}

// ---------------------------------------------------------------------------
// Gather v4: int8 rows (128B = one L2 line), DP4A dot engine.
// One z2 row per 8-LANE group; one warp LDG.128 pulls 4 complete rows / 4
// lines. Per iteration: 1 idx SHFL + 1 LDG + 4 DP4A + 3 int shuffle-adds.
// 8 iterations cover the warp's 32 negatives; lane (q,s) owns negative
// w*32 + 4*s + q, so each thread does exactly one __expf.
// The last block to finish performs the deterministic mean.
// ---------------------------------------------------------------------------
__global__ void __launch_bounds__(256)
gather_kernel(const int* __restrict__ raw, float* __restrict__ out) {
    __shared__ float s_red[8];
    __shared__ float s_sum[256];
    __shared__ bool  s_last;

    const int b    = blockIdx.x;
    const int t    = threadIdx.x;
    const int w    = t >> 5;
    const int lane = t & 31;
    const int s    = lane & 7;    // lane within 8-lane row group
    const int q    = lane >> 3;   // which of 4 rows per LDG wave

    // hoist the per-row scalars so their L2 latency overlaps the dot loop
    const float f1  = __ldg(&g_f1[b]);
    const float pos = __ldg(&g_pos[b]);

    // this lane's 16 z1 bytes (elements [s*16, s*16+16))
    const uint4 z1v =
        reinterpret_cast<const uint4*>(g_z1q)[(size_t)b * 8 + s];

    const int kbase = b * KN + w * 32 + lane;
    const int myidx = g_is64 ? raw[2 * kbase] : raw[kbase];

    int mydot = 0;
    #pragma unroll
    for (int i = 0; i < 8; i++) {
        const int row = __shfl_sync(0xffffffffu, myidx, 4 * i + q);
        const uint4 v = reinterpret_cast<const uint4*>(g_z2q)[(size_t)row * 8 + s];
        int acc;
        acc = __dp4a((int)v.x, (int)z1v.x, 0);
        acc = __dp4a((int)v.y, (int)z1v.y, acc);
        acc = __dp4a((int)v.z, (int)z1v.z, acc);
        acc = __dp4a((int)v.w, (int)z1v.w, acc);
        // reduce across the 8 lanes of this row group (consecutive lanes)
        acc += __shfl_xor_sync(0xffffffffu, acc, 4);
        acc += __shfl_xor_sync(0xffffffffu, acc, 2);
        acc += __shfl_xor_sync(0xffffffffu, acc, 1);
        if (s == i) mydot = acc;  // lane owns negative w*32 + 4*s + q
    }

    // |logit| <= ~14.3 -> no max-shift needed in fp32.
    float e = __expf((float)mydot * f1);
    #pragma unroll
    for (int o = 16; o; o >>= 1) e += __shfl_xor_sync(0xffffffffu, e, o);
    if (lane == 0) s_red[w] = e;
    __syncthreads();

    if (t == 0) {
        float tot = s_red[0] + s_red[1] + s_red[2] + s_red[3]
                  + s_red[4] + s_red[5] + s_red[6] + s_red[7];
        tot += __expf(pos);
        g_partial[b] = logf(tot) - pos;   // -log_softmax(logits)[0]
        __threadfence();
        const int c = atomicAdd(&g_count, 1);
        s_last = (c == BN - 1);
    }
    __syncthreads();

    // Last finishing block performs the mean (deterministic order).
    if (s_last) {
        const float4* p4 = reinterpret_cast<const float4*>(g_partial);
        float a = 0.0f;
        #pragma unroll
        for (int j = 0; j < 8; j++) {
            const float4 v = __ldcg(p4 + t + j * 256);
            a += (v.x + v.y) + (v.z + v.w);
        }
        s_sum[t] = a;
        __syncthreads();
        #pragma unroll
        for (int o = 128; o; o >>= 1) {
            if (t < o) s_sum[t] += s_sum[t + o];
            __syncthreads();
        }
        if (t == 0) out[0] = s_sum[0] / (float)BN;
    }
}

extern "C" void kernel_launch(void* const* d_in, const int* in_sizes, int n_in,
                              void* d_out, int out_size) {
    const float* z1  = (const float*)d_in[0];
    const float* z2  = (const float*)d_in[1];
    const int*   neg = (const int*)d_in[2];   // raw view; width detected on-device
    float* out = (float*)d_out;

    norm_kernel<<<BN / 8, 256>>>(z1, z2, neg);
    gather_kernel<<<BN, 256>>>(neg, out);
}